// round 1
// baseline (speedup 1.0000x reference)
#include <cuda_runtime.h>
#include <cuda_bf16.h>
#include <math.h>

#define NN   50000
#define EE   800000
#define ET   (EE + NN)      // 850000 edges incl. self loops
#define FDIM 128
#define NH   4
#define CH   32
#define NEG_SLOPE 0.2f

// ---------------- device scratch (module-load allocated, no cudaMalloc) ----
__device__ int   g_cnt[NN];
__device__ int   g_rowptr[NN + 1];
__device__ int   g_cursor[NN];
__device__ int   g_csr[ET];
__device__ int   g_bsums[256];

__device__ float g_hw[NN * FDIM];     // transformed features (current layer)
__device__ float g_f1[NN * FDIM];     // layer1 output
__device__ float g_f2[NN * FDIM];     // layer2 output
__device__ float g_alpha[NN * 2 * NH];// per-node alpha_src[0..3], alpha_dst[4..7]
__device__ float g_scr[ET * NH];      // per-edge scratch (alpha -> exp)
__device__ float g_hw3[NN * 2];
__device__ float g_a3[NN * 2];

// ---------------- warp reduce helpers --------------------------------------
__device__ __forceinline__ float wmax(float v) {
    #pragma unroll
    for (int o = 16; o; o >>= 1) v = fmaxf(v, __shfl_xor_sync(0xffffffffu, v, o));
    return v;
}
__device__ __forceinline__ float wsum(float v) {
    #pragma unroll
    for (int o = 16; o; o >>= 1) v += __shfl_xor_sync(0xffffffffu, v, o);
    return v;
}

// ---------------- CSR construction ------------------------------------------
__global__ void k_zero_cnt() {
    int i = blockIdx.x * blockDim.x + threadIdx.x;
    if (i < NN) g_cnt[i] = 0;
}

__global__ void k_hist(const int* __restrict__ ei) {
    int e = blockIdx.x * blockDim.x + threadIdx.x;
    if (e >= ET) return;
    int dst = (e < EE) ? ei[EE + e] : (e - EE);
    atomicAdd(&g_cnt[dst], 1);
}

__global__ void k_scan_block() {
    __shared__ int sm[256];
    int i = blockIdx.x * 256 + threadIdx.x;
    int v = (i < NN) ? g_cnt[i] : 0;
    sm[threadIdx.x] = v;
    __syncthreads();
    #pragma unroll
    for (int o = 1; o < 256; o <<= 1) {
        int t = (threadIdx.x >= o) ? sm[threadIdx.x - o] : 0;
        __syncthreads();
        sm[threadIdx.x] += t;
        __syncthreads();
    }
    if (i < NN) g_rowptr[i] = sm[threadIdx.x] - v;       // exclusive, block-local
    if (threadIdx.x == 255) g_bsums[blockIdx.x] = sm[255];
}

__global__ void k_scan_tops(int nb) {
    __shared__ int sm[256];
    int v = (threadIdx.x < nb) ? g_bsums[threadIdx.x] : 0;
    sm[threadIdx.x] = v;
    __syncthreads();
    #pragma unroll
    for (int o = 1; o < 256; o <<= 1) {
        int t = (threadIdx.x >= o) ? sm[threadIdx.x - o] : 0;
        __syncthreads();
        sm[threadIdx.x] += t;
        __syncthreads();
    }
    g_bsums[threadIdx.x] = sm[threadIdx.x] - v;          // exclusive
}

__global__ void k_scan_finish() {
    int i = blockIdx.x * blockDim.x + threadIdx.x;
    if (i < NN) {
        int r = g_rowptr[i] + g_bsums[i >> 8];
        g_rowptr[i] = r;
        g_cursor[i] = r;
    }
    if (i == 0) g_rowptr[NN] = ET;
}

__global__ void k_scatter(const int* __restrict__ ei) {
    int e = blockIdx.x * blockDim.x + threadIdx.x;
    if (e >= ET) return;
    int src, dst;
    if (e < EE) { src = ei[e]; dst = ei[EE + e]; }
    else        { src = dst = e - EE; }
    int p = atomicAdd(&g_cursor[dst], 1);
    g_csr[p] = src;
}

// ---------------- GEMM: C[M,128] = A[M,128] @ W[128,128] --------------------
__global__ void k_gemm128(const float* __restrict__ A, const float* __restrict__ W,
                          float* __restrict__ C, int M) {
    __shared__ float As[64][32];
    __shared__ float Ws[32][128];
    int t    = threadIdx.x;          // 256 threads
    int row0 = blockIdx.x * 64;
    int lane = t & 31;
    int rg   = t >> 5;               // row group 0..7 (rows rg*8 .. rg*8+7)
    int col  = lane * 4;

    float acc[8][4];
    #pragma unroll
    for (int r = 0; r < 8; r++)
        #pragma unroll
        for (int j = 0; j < 4; j++) acc[r][j] = 0.f;

    for (int k0 = 0; k0 < 128; k0 += 32) {
        #pragma unroll
        for (int u = 0; u < 2; u++) {
            int idx = t + u * 256;           // 0..511 float4s of A tile
            int r   = idx >> 3;
            int c4  = (idx & 7) * 4;
            int gr  = row0 + r;
            float4 v = (gr < M) ? *(const float4*)&A[gr * 128 + k0 + c4]
                                : make_float4(0.f, 0.f, 0.f, 0.f);
            *(float4*)&As[r][c4] = v;
        }
        #pragma unroll
        for (int u = 0; u < 4; u++) {
            int idx = t + u * 256;           // 0..1023 float4s of W tile
            int r   = idx >> 5;
            int c4  = (idx & 31) * 4;
            *(float4*)&Ws[r][c4] = *(const float4*)&W[(k0 + r) * 128 + c4];
        }
        __syncthreads();
        #pragma unroll
        for (int kk = 0; kk < 32; kk++) {
            float4 b = *(float4*)&Ws[kk][col];
            #pragma unroll
            for (int r = 0; r < 8; r++) {
                float a = As[rg * 8 + r][kk];
                acc[r][0] += a * b.x;
                acc[r][1] += a * b.y;
                acc[r][2] += a * b.z;
                acc[r][3] += a * b.w;
            }
        }
        __syncthreads();
    }
    #pragma unroll
    for (int r = 0; r < 8; r++) {
        int gr = row0 + rg * 8 + r;
        if (gr < M)
            *(float4*)&C[gr * 128 + col] =
                make_float4(acc[r][0], acc[r][1], acc[r][2], acc[r][3]);
    }
}

// ---------------- per-node alpha (H=4, C=32) --------------------------------
__global__ void k_alpha4(const float* __restrict__ hw,
                         const float* __restrict__ asrc,
                         const float* __restrict__ adst) {
    int n = (blockIdx.x * blockDim.x + threadIdx.x) >> 5;
    if (n >= NN) return;
    int lane = threadIdx.x & 31;
    #pragma unroll
    for (int h = 0; h < NH; h++) {
        float v  = hw[n * FDIM + h * CH + lane];
        float ps = wsum(v * asrc[h * CH + lane]);
        float pd = wsum(v * adst[h * CH + lane]);
        if (lane == 0) {
            g_alpha[n * 8 + h]     = ps;
            g_alpha[n * 8 + 4 + h] = pd;
        }
    }
}

// ---------------- edge softmax + aggregation (H=4, C=32) --------------------
__global__ void k_aggregate4(const float* __restrict__ hw,
                             const float* __restrict__ bias,
                             float* __restrict__ out, int applyElu) {
    int n = (blockIdx.x * blockDim.x + threadIdx.x) >> 5;
    if (n >= NN) return;
    int lane = threadIdx.x & 31;
    int s0 = g_rowptr[n], s1 = g_rowptr[n + 1];

    float ad[NH];
    #pragma unroll
    for (int h = 0; h < NH; h++) ad[h] = g_alpha[n * 8 + 4 + h];

    // pass 1: alpha = leakyrelu(as[src] + ad[dst]); running max
    float m[NH];
    #pragma unroll
    for (int h = 0; h < NH; h++) m[h] = -3.4e38f;
    for (int i = s0 + lane; i < s1; i += 32) {
        int s = g_csr[i];
        #pragma unroll
        for (int h = 0; h < NH; h++) {
            float a = g_alpha[s * 8 + h] + ad[h];
            a = (a > 0.f) ? a : NEG_SLOPE * a;
            g_scr[i * NH + h] = a;
            m[h] = fmaxf(m[h], a);
        }
    }
    #pragma unroll
    for (int h = 0; h < NH; h++) m[h] = wmax(m[h]);

    // pass 2: e = exp(alpha - max); denom
    float sum[NH];
    #pragma unroll
    for (int h = 0; h < NH; h++) sum[h] = 0.f;
    for (int i = s0 + lane; i < s1; i += 32) {
        #pragma unroll
        for (int h = 0; h < NH; h++) {
            float e = __expf(g_scr[i * NH + h] - m[h]);
            g_scr[i * NH + h] = e;
            sum[h] += e;
        }
    }
    float inv[NH];
    #pragma unroll
    for (int h = 0; h < NH; h++) inv[h] = 1.f / wsum(sum[h]);
    __syncwarp();

    // pass 3: weighted gather-accumulate, lane = channel
    float acc[NH];
    #pragma unroll
    for (int h = 0; h < NH; h++) acc[h] = 0.f;
    for (int i = s0; i < s1; i++) {
        int s = g_csr[i];                    // broadcast load
        #pragma unroll
        for (int h = 0; h < NH; h++) {
            float w = g_scr[i * NH + h] * inv[h];
            acc[h] += w * hw[s * FDIM + h * CH + lane];
        }
    }
    #pragma unroll
    for (int h = 0; h < NH; h++) {
        float v = acc[h] + bias[h * CH + lane];
        if (applyElu) v = (v > 0.f) ? v : (__expf(v) - 1.f);
        out[n * FDIM + h * CH + lane] = v;
    }
}

// ---------------- layer 3: GEMM [N,128]@[128,2] -----------------------------
__global__ void k_gemm_w3(const float* __restrict__ in, const float* __restrict__ W3) {
    int n = (blockIdx.x * blockDim.x + threadIdx.x) >> 5;
    if (n >= NN) return;
    int lane = threadIdx.x & 31;
    const float* r = in + n * FDIM;
    float a0 = 0.f, a1 = 0.f;
    for (int k = lane; k < FDIM; k += 32) {
        float v = r[k];
        a0 += v * W3[2 * k];
        a1 += v * W3[2 * k + 1];
    }
    a0 = wsum(a0); a1 = wsum(a1);
    if (lane == 0) { g_hw3[n * 2] = a0; g_hw3[n * 2 + 1] = a1; }
}

__global__ void k_alpha3(const float* __restrict__ as3, const float* __restrict__ ad3) {
    int n = blockIdx.x * blockDim.x + threadIdx.x;
    if (n >= NN) return;
    float h0 = g_hw3[n * 2], h1 = g_hw3[n * 2 + 1];
    g_a3[n * 2]     = h0 * as3[0] + h1 * as3[1];
    g_a3[n * 2 + 1] = h0 * ad3[0] + h1 * ad3[1];
}

// layer-3 aggregate (H=1,C=2) + bias + log_softmax, writes final output
__global__ void k_aggregate1(const float* __restrict__ b3, float* __restrict__ out) {
    int n = (blockIdx.x * blockDim.x + threadIdx.x) >> 5;
    if (n >= NN) return;
    int lane = threadIdx.x & 31;
    int s0 = g_rowptr[n], s1 = g_rowptr[n + 1];
    float ad = g_a3[n * 2 + 1];

    float m = -3.4e38f;
    for (int i = s0 + lane; i < s1; i += 32) {
        int s = g_csr[i];
        float a = g_a3[s * 2] + ad;
        a = (a > 0.f) ? a : NEG_SLOPE * a;
        g_scr[i] = a;
        m = fmaxf(m, a);
    }
    m = wmax(m);

    float sum = 0.f;
    for (int i = s0 + lane; i < s1; i += 32) {
        float e = __expf(g_scr[i] - m);
        g_scr[i] = e;
        sum += e;
    }
    float inv = 1.f / wsum(sum);
    __syncwarp();

    float a0 = 0.f, a1 = 0.f;
    for (int i = s0 + lane; i < s1; i += 32) {
        int s = g_csr[i];
        float w = g_scr[i] * inv;
        a0 += w * g_hw3[s * 2];
        a1 += w * g_hw3[s * 2 + 1];
    }
    a0 = wsum(a0); a1 = wsum(a1);

    if (lane == 0) {
        float z0 = a0 + b3[0];
        float z1 = a1 + b3[1];
        float mx = fmaxf(z0, z1);
        float l  = logf(__expf(z0 - mx) + __expf(z1 - mx));
        out[n * 2]     = z0 - mx - l;
        out[n * 2 + 1] = z1 - mx - l;
    }
}

// ---------------- host driver -----------------------------------------------
extern "C" void kernel_launch(void* const* d_in, const int* in_sizes, int n_in,
                              void* d_out, int out_size) {
    const float* x   = (const float*)d_in[0];
    const int*   ei  = (const int*)  d_in[1];
    const float* W1  = (const float*)d_in[2];
    const float* as1 = (const float*)d_in[3];
    const float* ad1 = (const float*)d_in[4];
    const float* b1  = (const float*)d_in[5];
    const float* W2  = (const float*)d_in[6];
    const float* as2 = (const float*)d_in[7];
    const float* ad2 = (const float*)d_in[8];
    const float* b2  = (const float*)d_in[9];
    const float* W3  = (const float*)d_in[10];
    const float* as3 = (const float*)d_in[11];
    const float* ad3 = (const float*)d_in[12];
    const float* b3  = (const float*)d_in[13];
    float* out = (float*)d_out;

    float *p_hw, *p_f1, *p_f2;
    cudaGetSymbolAddress((void**)&p_hw, g_hw);
    cudaGetSymbolAddress((void**)&p_f1, g_f1);
    cudaGetSymbolAddress((void**)&p_f2, g_f2);

    const int TPB = 256;
    int nbN  = (NN + TPB - 1) / TPB;          // 196
    int nbE  = (ET + TPB - 1) / TPB;          // 3321
    int nbW  = (NN * 32 + TPB - 1) / TPB;     // 6250 (warp per node)
    int nbG  = (NN + 63) / 64;                // 782 (gemm tiles)

    // CSR build
    k_zero_cnt<<<nbN, TPB>>>();
    k_hist<<<nbE, TPB>>>(ei);
    k_scan_block<<<nbN, TPB>>>();
    k_scan_tops<<<1, 256>>>(nbN);
    k_scan_finish<<<nbN, TPB>>>();
    k_scatter<<<nbE, TPB>>>(ei);

    // layer 1
    k_gemm128<<<nbG, TPB>>>(x, W1, p_hw, NN);
    k_alpha4<<<nbW, TPB>>>(p_hw, as1, ad1);
    k_aggregate4<<<nbW, TPB>>>(p_hw, b1, p_f1, 1);

    // layer 2
    k_gemm128<<<nbG, TPB>>>(p_f1, W2, p_hw, NN);
    k_alpha4<<<nbW, TPB>>>(p_hw, as2, ad2);
    k_aggregate4<<<nbW, TPB>>>(p_hw, b2, p_f2, 1);

    // layer 3
    k_gemm_w3<<<nbW, TPB>>>(p_f2, W3);
    k_alpha3<<<nbN, TPB>>>(as3, ad3);
    k_aggregate1<<<nbW, TPB>>>(b3, out);
}